// round 12
// baseline (speedup 1.0000x reference)
#include <cuda_runtime.h>
#include <cuda_fp16.h>
#include <cstdint>

#define DIMZ 64
#define HID 256
#define NBATCH 32768
#define NSTEPS 100
#define TILE_M 128
#define NTILES 256
#define NTHREADS 288   // 8 worker warps + 1 MMA warp
#define DT_F 0.01f

#if defined(__CUDA_ARCH__)
#if defined(__CUDA_ARCH_FEAT_SM103_ALL) || \
    (defined(__CUDA_ARCH_SPECIFIC__) && (__CUDA_ARCH_SPECIFIC__ == 1030)) || \
    (defined(__CUDA_ARCH_HAS_FEATURE__) && defined(__CUDA_ARCH_FEAT_SM101_ALL))
#define CNF_HAS_TCGEN05 1
#else
#define CNF_HAS_TCGEN05 0
#endif
#else
#define CNF_HAS_TCGEN05 0
#endif

// ---- TMEM columns ----
// [0,64)    D0   : G1h0 D lo / G2 Q0 / G2 Q3
// [64,128)  D1   : G1h0 D hi / G2 Q1
// [128,256) AH1  : layer-1 activations f16 packed
// [256,384) DW1  : G1h1 D (f32) -> reused as AH2 (f16 packed)
// [384,448) D2   : G2 Q2 -> reused as D3 (G3 f32 D)
// [448,480) AZ   : z input f16 packed
#define TMEM_NCOLS 512u

// ---- named HW barriers ----
#define BAR_Z 1     // 288
#define BAR_H1A 2   // 160 (wg0 + MMA)
#define BAR_H1 3    // 288
#define BAR_F0 4    // 160 (wg0 + MMA)
#define BAR_H2B 5   // 288
#define BAR_H2 6    // 288

// ---- SMEM byte layout ----
#define SM_TMEMPTR 0
#define SM_C0 8
#define SM_C1 16
#define SM_C2 24
#define SM_C3 32
#define SM_CA 40
#define SM_CB 48
#define SM_B1H 96
#define SM_B2H 608
#define SM_B3F 1120
#define SM_W1 2048
#define SM_W2 34816
#define SM_W3 165888
#define SM_TOTAL 198656

#define IDESC_F_N128 0x08200010u
#define IDESC_F_N64 0x08100010u
#define IDESC_F_N32 0x08080010u

static constexpr uint64_t DESC_BASE_SW128 =
    (uint64_t(2) << 61) | (uint64_t(1) << 46) | (uint64_t(64) << 32) | (uint64_t(1) << 16);

#if CNF_HAS_TCGEN05

__device__ __forceinline__ uint32_t smem_u32(const void* p) {
    uint32_t a;
    asm("{ .reg .u64 t; cvta.to.shared.u64 t, %1; cvt.u32.u64 %0, t; }" : "=r"(a) : "l"(p));
    return a;
}
__device__ __forceinline__ uint32_t elect1() {
    uint32_t r;
    asm volatile("{ .reg .pred p; elect.sync _|p, 0xFFFFFFFF; selp.b32 %0, 1, 0, p; }" : "=r"(r));
    return r;
}
__device__ __forceinline__ uint32_t swz128(uint32_t x) { return x ^ ((x >> 3) & 0x70); }

__device__ __forceinline__ uint32_t pack_f16x2(float lo, float hi) {
    uint32_t d;
    asm("cvt.rn.f16x2.f32 %0, %1, %2;" : "=r"(d) : "f"(hi), "f"(lo));
    return d;
}
__device__ __forceinline__ uint32_t hadd2u(uint32_t a, uint32_t b) {
    uint32_t d;
    asm("add.rn.f16x2 %0, %1, %2;" : "=r"(d) : "r"(a), "r"(b));
    return d;
}
__device__ __forceinline__ uint32_t htanh2(uint32_t a) {
    uint32_t d;
    asm("tanh.approx.f16x2 %0, %1;" : "=r"(d) : "r"(a));
    return d;
}

#define TCGEN05_ALLOC(smem_addr, nCols) \
    asm volatile("tcgen05.alloc.cta_group::1.sync.aligned.shared::cta.b32 [%0], %1;" \
                 :: "r"((uint32_t)(smem_addr)), "r"((uint32_t)(nCols)) : "memory")
#define TCGEN05_DEALLOC(tmem_addr, nCols) \
    asm volatile("tcgen05.dealloc.cta_group::1.sync.aligned.b32 %0, %1;" \
                 :: "r"(tmem_addr), "r"((uint32_t)(nCols)))
#define TCGEN05_WAIT_LD() asm volatile("tcgen05.wait::ld.sync.aligned;" ::: "memory")
#define TCGEN05_WAIT_ST() asm volatile("tcgen05.wait::st.sync.aligned;" ::: "memory")
#define TCGEN05_FENCE_BEFORE() asm volatile("tcgen05.fence::before_thread_sync;" ::: "memory")
#define TCGEN05_FENCE_AFTER() asm volatile("tcgen05.fence::after_thread_sync;" ::: "memory")
#define TCGEN05_COMMIT(mbar) \
    asm volatile("tcgen05.commit.cta_group::1.mbarrier::arrive::one.shared::cluster.b64 [%0];" \
                 :: "r"((uint32_t)(mbar)) : "memory")
#define MBARRIER_INIT(mbar, count) \
    asm volatile("mbarrier.init.shared.b64 [%0], %1;" \
                 :: "r"((uint32_t)(mbar)), "r"((uint32_t)(count)) : "memory")
#define FENCE_PROXY_ASYNC() asm volatile("fence.proxy.async.shared::cta;" ::: "memory")
#define BAR_ARRIVE(id, cnt) \
    asm volatile("bar.arrive %0, %1;" :: "r"((uint32_t)(id)), "r"((uint32_t)(cnt)) : "memory")
#define BAR_SYNC_N(id, cnt) \
    asm volatile("bar.sync %0, %1;" :: "r"((uint32_t)(id)), "r"((uint32_t)(cnt)) : "memory")

#define MBARRIER_WAIT_PARITY(mbar_smem_addr, phase_parity) do { \
    uint32_t _mbar = (uint32_t)(mbar_smem_addr); \
    uint32_t _parity = (uint32_t)(phase_parity); \
    uint32_t _done; \
    asm volatile( \
        "{\n\t" \
        ".reg .pred p;\n\t" \
        "mbarrier.try_wait.parity.acquire.cta.shared::cta.b64 p, [%1], %2;\n\t" \
        "selp.b32 %0, 1, 0, p;\n\t" \
        "}" \
        : "=r"(_done) : "r"(_mbar), "r"(_parity) : "memory"); \
    if (!_done) { \
        asm volatile( \
            "{\n\t" \
            ".reg .pred P1;\n\t" \
            "WAIT_LOOP_%=:\n\t" \
            "mbarrier.try_wait.parity.acquire.cta.shared::cta.b64 P1, [%0], %1, 0x989680;\n\t" \
            "@P1 bra.uni WAIT_DONE_%=;\n\t" \
            "bra.uni WAIT_LOOP_%=;\n\t" \
            "WAIT_DONE_%=:\n\t" \
            "}" \
            :: "r"(_mbar), "r"(_parity) : "memory"); \
    } \
} while (0)

#define TCGEN05_LD_32X32B_X32(r, tmem_addr) \
    asm volatile( \
        "tcgen05.ld.sync.aligned.32x32b.x32.b32 " \
        "{%0, %1, %2, %3, %4, %5, %6, %7, " \
        " %8, %9, %10, %11, %12, %13, %14, %15, " \
        " %16, %17, %18, %19, %20, %21, %22, %23, " \
        " %24, %25, %26, %27, %28, %29, %30, %31}, [%32];" \
        : "=r"((r)[0]),  "=r"((r)[1]),  "=r"((r)[2]),  "=r"((r)[3]), \
          "=r"((r)[4]),  "=r"((r)[5]),  "=r"((r)[6]),  "=r"((r)[7]), \
          "=r"((r)[8]),  "=r"((r)[9]),  "=r"((r)[10]), "=r"((r)[11]), \
          "=r"((r)[12]), "=r"((r)[13]), "=r"((r)[14]), "=r"((r)[15]), \
          "=r"((r)[16]), "=r"((r)[17]), "=r"((r)[18]), "=r"((r)[19]), \
          "=r"((r)[20]), "=r"((r)[21]), "=r"((r)[22]), "=r"((r)[23]), \
          "=r"((r)[24]), "=r"((r)[25]), "=r"((r)[26]), "=r"((r)[27]), \
          "=r"((r)[28]), "=r"((r)[29]), "=r"((r)[30]), "=r"((r)[31]) \
        : "r"(tmem_addr))

#define TCGEN05_ST_32X32B_X16(tmem_addr, r) \
    asm volatile( \
        "tcgen05.st.sync.aligned.32x32b.x16.b32 [%0], " \
        "{%1, %2, %3, %4, %5, %6, %7, %8, " \
        " %9, %10, %11, %12, %13, %14, %15, %16};" \
        :: "r"(tmem_addr), \
           "r"((r)[0]),  "r"((r)[1]),  "r"((r)[2]),  "r"((r)[3]), \
           "r"((r)[4]),  "r"((r)[5]),  "r"((r)[6]),  "r"((r)[7]), \
           "r"((r)[8]),  "r"((r)[9]),  "r"((r)[10]), "r"((r)[11]), \
           "r"((r)[12]), "r"((r)[13]), "r"((r)[14]), "r"((r)[15]) \
        : "memory")

__device__ __forceinline__ void mma_f16_ts(uint32_t d, uint32_t a, uint64_t bdesc,
                                           uint32_t idesc, uint32_t accum) {
    asm volatile(
        "{\n\t"
        ".reg .pred p;\n\t"
        "setp.ne.u32 p, %5, 0;\n\t"
        "tcgen05.mma.cta_group::1.kind::f16 [%0], [%1], %2, %3, {%4, %4, %4, %4}, p;\n\t"
        "}"
        :: "r"(d), "r"(a), "l"(bdesc), "r"(idesc), "r"(0u), "r"(accum)
        : "memory");
}

// Paired 64-col epilogue: LDTM dsrc and dsrc+32 (this warp's subpartition),
// pack+bias+tanh, STTM 32 packed cols at adst/adst+16. Ends drained.
__device__ __forceinline__ void epi_pair(uint32_t tb, uint32_t dsrc, uint32_t adst,
                                         const uint32_t* bias32, uint32_t warpoff) {
    uint32_t r0[32], r1[32];
    TCGEN05_LD_32X32B_X32(r0, tb + dsrc + warpoff);
    TCGEN05_LD_32X32B_X32(r1, tb + dsrc + 32u + warpoff);
    TCGEN05_WAIT_LD();
    uint32_t o[16];
#pragma unroll
    for (int j = 0; j < 16; j++) {
        uint32_t p = pack_f16x2(__uint_as_float(r0[2 * j]), __uint_as_float(r0[2 * j + 1]));
        o[j] = htanh2(hadd2u(p, bias32[j]));
    }
    TCGEN05_ST_32X32B_X16(tb + adst + warpoff, o);
#pragma unroll
    for (int j = 0; j < 16; j++) {
        uint32_t p = pack_f16x2(__uint_as_float(r1[2 * j]), __uint_as_float(r1[2 * j + 1]));
        o[j] = htanh2(hadd2u(p, bias32[16 + j]));
    }
    TCGEN05_ST_32X32B_X16(tb + adst + 16u + warpoff, o);
    TCGEN05_WAIT_ST();
}

#endif  // CNF_HAS_TCGEN05

extern "C" __global__ void __launch_bounds__(NTHREADS, 1)
cnf_rk4_kernel(const float* __restrict__ z0,
               const float* __restrict__ W1, const float* __restrict__ b1,
               const float* __restrict__ W2, const float* __restrict__ b2,
               const float* __restrict__ W3, const float* __restrict__ b3,
               float* __restrict__ out) {
#if CNF_HAS_TCGEN05
    extern __shared__ char smem[];
    const uint32_t sb = smem_u32(smem);
    const int tid = threadIdx.x;
    const int w = tid >> 5;
    const int lane = tid & 31;

    if (w == 8) TCGEN05_ALLOC(sb + SM_TMEMPTR, TMEM_NCOLS);

    // ---- Weights -> f16 B-operand layouts in SMEM ----
    for (int i = tid; i < 64 * 256; i += NTHREADS) {
        int k = i >> 8, n = i & 255;
        *(__half*)(smem + SM_W1 + swz128((uint32_t)(n * 128 + k * 2))) = __float2half_rn(W1[i]);
    }
    for (int i = tid; i < 256 * 256; i += NTHREADS) {
        int k = i >> 8, n = i & 255;
        uint32_t off = (uint32_t)((((n >> 3) + (k >> 6) * 32) << 10) + ((n & 7) << 7) + ((k & 63) << 1));
        *(__half*)(smem + SM_W2 + swz128(off)) = __float2half_rn(W2[i]);
    }
    for (int i = tid; i < 256 * 64; i += NTHREADS) {
        int k = i >> 6, n = i & 63;
        uint32_t off = (uint32_t)((((n >> 3) + (k >> 6) * 8) << 10) + ((n & 7) << 7) + ((k & 63) << 1));
        *(__half*)(smem + SM_W3 + swz128(off)) = __float2half_rn(W3[i]);
    }
    for (int i = tid; i < 128; i += NTHREADS) {
        ((uint32_t*)(smem + SM_B1H))[i] = pack_f16x2(b1[2 * i], b1[2 * i + 1]);
        ((uint32_t*)(smem + SM_B2H))[i] = pack_f16x2(b2[2 * i], b2[2 * i + 1]);
    }
    for (int i = tid; i < 64; i += NTHREADS) ((float*)(smem + SM_B3F))[i] = b3[i];

    if (tid == 0) {
        MBARRIER_INIT(sb + SM_C0, 1); MBARRIER_INIT(sb + SM_C1, 1);
        MBARRIER_INIT(sb + SM_C2, 1); MBARRIER_INIT(sb + SM_C3, 1);
        MBARRIER_INIT(sb + SM_CA, 1); MBARRIER_INIT(sb + SM_CB, 1);
    }
    FENCE_PROXY_ASYNC();
    __syncthreads();

    uint32_t tb;
    asm volatile("ld.shared.b32 %0, [%1];" : "=r"(tb) : "r"(sb + SM_TMEMPTR));

    if (w == 8) {
        // ================= MMA-issue warp =================
        const uint64_t dW1 = DESC_BASE_SW128 | (((uint64_t)((sb + SM_W1) >> 4)) & 0x3FFF);
        const uint64_t dW2 = DESC_BASE_SW128 | (((uint64_t)((sb + SM_W2) >> 4)) & 0x3FFF);
        const uint64_t dW3 = DESC_BASE_SW128 | (((uint64_t)((sb + SM_W3) >> 4)) & 0x3FFF);
        const uint64_t dW1b = dW1 + 1024;
        const uint64_t dW3b = dW3 + 256;

        for (int it = 0; it < NSTEPS * 4; ++it) {
            // P1: AZ ready -> G1 both halves
            BAR_SYNC_N(BAR_Z, 288);
            TCGEN05_FENCE_AFTER();
            if (elect1()) {
                mma_f16_ts(tb + 0u,   tb + 448u,       dW1,      IDESC_F_N128, 0);
                mma_f16_ts(tb + 0u,   tb + 448u + 8u,  dW1 + 2,  IDESC_F_N128, 1);
                mma_f16_ts(tb + 0u,   tb + 448u + 16u, dW1 + 4,  IDESC_F_N128, 1);
                mma_f16_ts(tb + 0u,   tb + 448u + 24u, dW1 + 6,  IDESC_F_N128, 1);
                TCGEN05_COMMIT(sb + SM_C0);
                mma_f16_ts(tb + 256u, tb + 448u,       dW1b,     IDESC_F_N128, 0);
                mma_f16_ts(tb + 256u, tb + 448u + 8u,  dW1b + 2, IDESC_F_N128, 1);
                mma_f16_ts(tb + 256u, tb + 448u + 16u, dW1b + 4, IDESC_F_N128, 1);
                mma_f16_ts(tb + 256u, tb + 448u + 24u, dW1b + 6, IDESC_F_N128, 1);
                TCGEN05_COMMIT(sb + SM_C1);
            }
            // P2: AH1 low half (wg0) -> Q0/Q1/Q2 K0-7
            BAR_SYNC_N(BAR_H1A, 160);
            TCGEN05_FENCE_AFTER();
            if (elect1()) {
#pragma unroll
                for (int ks = 0; ks < 8; ks++)
                    mma_f16_ts(tb + 0u, tb + 128u + (uint32_t)(ks * 8),
                               dW2 + (uint64_t)((ks & 3) * 2 + (ks >> 2) * 2048), IDESC_F_N64, ks > 0);
#pragma unroll
                for (int ks = 0; ks < 8; ks++)
                    mma_f16_ts(tb + 64u, tb + 128u + (uint32_t)(ks * 8),
                               dW2 + (uint64_t)(512 + (ks & 3) * 2 + (ks >> 2) * 2048), IDESC_F_N64, ks > 0);
#pragma unroll
                for (int ks = 0; ks < 8; ks++)
                    mma_f16_ts(tb + 384u, tb + 128u + (uint32_t)(ks * 8),
                               dW2 + (uint64_t)(1024 + (ks & 3) * 2 + (ks >> 2) * 2048), IDESC_F_N64, ks > 0);
            }
            // P3: AH1 full -> Q0/Q1/Q2 K8-15 (+C0, +C1, +C2)
            BAR_SYNC_N(BAR_H1, 288);
            TCGEN05_FENCE_AFTER();
            if (elect1()) {
#pragma unroll
                for (int ks = 8; ks < 16; ks++)
                    mma_f16_ts(tb + 0u, tb + 128u + (uint32_t)(ks * 8),
                               dW2 + (uint64_t)((ks & 3) * 2 + (ks >> 2) * 2048), IDESC_F_N64, 1);
                TCGEN05_COMMIT(sb + SM_C0);
#pragma unroll
                for (int ks = 8; ks < 16; ks++)
                    mma_f16_ts(tb + 64u, tb + 128u + (uint32_t)(ks * 8),
                               dW2 + (uint64_t)(512 + (ks & 3) * 2 + (ks >> 2) * 2048), IDESC_F_N64, 1);
                TCGEN05_COMMIT(sb + SM_C1);
#pragma unroll
                for (int ks = 8; ks < 16; ks++)
                    mma_f16_ts(tb + 384u, tb + 128u + (uint32_t)(ks * 8),
                               dW2 + (uint64_t)(1024 + (ks & 3) * 2 + (ks >> 2) * 2048), IDESC_F_N64, 1);
                TCGEN05_COMMIT(sb + SM_C2);
            }
            // P4: D0 reads drained (wg0 q0) -> Q3 (+C3)
            BAR_SYNC_N(BAR_F0, 160);
            TCGEN05_FENCE_AFTER();
            if (elect1()) {
#pragma unroll
                for (int ks = 0; ks < 16; ks++)
                    mma_f16_ts(tb + 0u, tb + 128u + (uint32_t)(ks * 8),
                               dW2 + (uint64_t)(1536 + (ks & 3) * 2 + (ks >> 2) * 2048), IDESC_F_N64, ks > 0);
                TCGEN05_COMMIT(sb + SM_C3);
            }
            // P5: q0/q1 stored + q2 LD-drained -> G3 n0/n1 K0-7
            BAR_SYNC_N(BAR_H2B, 288);
            TCGEN05_FENCE_AFTER();
            if (elect1()) {
#pragma unroll
                for (int ks = 0; ks < 8; ks++)
                    mma_f16_ts(tb + 384u, tb + 256u + (uint32_t)(ks * 8),
                               dW3 + (uint64_t)((ks & 3) * 2 + (ks >> 2) * 512), IDESC_F_N32, ks > 0);
#pragma unroll
                for (int ks = 0; ks < 8; ks++)
                    mma_f16_ts(tb + 416u, tb + 256u + (uint32_t)(ks * 8),
                               dW3b + (uint64_t)((ks & 3) * 2 + (ks >> 2) * 512), IDESC_F_N32, ks > 0);
            }
            // P6: AH2 full -> finish G3 (+CA, +CB)
            BAR_SYNC_N(BAR_H2, 288);
            TCGEN05_FENCE_AFTER();
            if (elect1()) {
#pragma unroll
                for (int ks = 8; ks < 16; ks++)
                    mma_f16_ts(tb + 384u, tb + 256u + (uint32_t)(ks * 8),
                               dW3 + (uint64_t)((ks & 3) * 2 + (ks >> 2) * 512), IDESC_F_N32, 1);
                TCGEN05_COMMIT(sb + SM_CA);
#pragma unroll
                for (int ks = 8; ks < 16; ks++)
                    mma_f16_ts(tb + 416u, tb + 256u + (uint32_t)(ks * 8),
                               dW3b + (uint64_t)((ks & 3) * 2 + (ks >> 2) * 512), IDESC_F_N32, 1);
                TCGEN05_COMMIT(sb + SM_CB);
            }
        }
    } else {
        // ================= worker warps (0-7), stage-split by warpgroup =================
        const int sp = w & 3;
        const int wg = w >> 2;
        const uint32_t warpoff = (uint32_t)sp << 21;
        const uint32_t wg32 = (uint32_t)(wg * 32);
        const uint32_t wg16 = (uint32_t)(wg * 16);

        const uint32_t* bh1 = (const uint32_t*)(smem + SM_B1H);
        const uint32_t* bh2 = (const uint32_t*)(smem + SM_B2H);
        const float* b3s = (const float*)(smem + SM_B3F) + wg * 32;

        const int row = blockIdx.x * TILE_M + sp * 32 + lane;
        float zc[32], acc[32];
        {
            const float4* zp = (const float4*)(z0 + (size_t)row * DIMZ + wg * 32);
#pragma unroll
            for (int q = 0; q < 8; q++) {
                float4 v = zp[q];
                zc[4 * q] = v.x; zc[4 * q + 1] = v.y; zc[4 * q + 2] = v.z; zc[4 * q + 3] = v.w;
            }
#pragma unroll
            for (int j = 0; j < 32; j++) acc[j] = 0.0f;
        }
        // initial AZ (each wg writes its half)
        {
            uint32_t o[16];
#pragma unroll
            for (int j = 0; j < 16; j++) o[j] = pack_f16x2(zc[2 * j], zc[2 * j + 1]);
            TCGEN05_ST_32X32B_X16(tb + 448u + wg16 + warpoff, o);
            TCGEN05_WAIT_ST();
            TCGEN05_FENCE_BEFORE();
            BAR_ARRIVE(BAR_Z, 288);
        }

        if (wg == 0) {
            // ---- wg0 chain: E1h0, E2q0, E2q2, E3-lo ----
            uint32_t pc0 = 0, pc2 = 0, pca = 0;
            for (int it = 0; it < NSTEPS * 4; ++it) {
                const int s = it & 3;

                // E1h0: D[0,128) -> AH1[0:64packed] (cols 128-191)
                MBARRIER_WAIT_PARITY(sb + SM_C0, pc0); pc0 ^= 1u;
                TCGEN05_FENCE_AFTER();
                epi_pair(tb, 0u,  128u, bh1 + 0,  warpoff);
                epi_pair(tb, 64u, 160u, bh1 + 32, warpoff);
                TCGEN05_FENCE_BEFORE();
                BAR_ARRIVE(BAR_H1A, 160);
                BAR_ARRIVE(BAR_H1, 288);

                // E2q0: D0 -> AH2[0:32packed] (cols 256-287); early F0 after LD drain
                MBARRIER_WAIT_PARITY(sb + SM_C0, pc0); pc0 ^= 1u;
                TCGEN05_FENCE_AFTER();
                {
                    uint32_t r0[32], r1[32];
                    TCGEN05_LD_32X32B_X32(r0, tb + 0u + warpoff);
                    TCGEN05_LD_32X32B_X32(r1, tb + 32u + warpoff);
                    TCGEN05_WAIT_LD();
                    TCGEN05_FENCE_BEFORE();
                    BAR_ARRIVE(BAR_F0, 160);
                    uint32_t o[16];
#pragma unroll
                    for (int j = 0; j < 16; j++) {
                        uint32_t p = pack_f16x2(__uint_as_float(r0[2 * j]), __uint_as_float(r0[2 * j + 1]));
                        o[j] = htanh2(hadd2u(p, bh2[j]));
                    }
                    TCGEN05_ST_32X32B_X16(tb + 256u + warpoff, o);
#pragma unroll
                    for (int j = 0; j < 16; j++) {
                        uint32_t p = pack_f16x2(__uint_as_float(r1[2 * j]), __uint_as_float(r1[2 * j + 1]));
                        o[j] = htanh2(hadd2u(p, bh2[16 + j]));
                    }
                    TCGEN05_ST_32X32B_X16(tb + 272u + warpoff, o);
                    TCGEN05_WAIT_ST();
                }

                // E2q2: D2=[384,448) -> AH2[64:96packed] (cols 320-351); early H2B after LD drain
                MBARRIER_WAIT_PARITY(sb + SM_C2, pc2); pc2 ^= 1u;
                TCGEN05_FENCE_AFTER();
                {
                    uint32_t r0[32], r1[32];
                    TCGEN05_LD_32X32B_X32(r0, tb + 384u + warpoff);
                    TCGEN05_LD_32X32B_X32(r1, tb + 416u + warpoff);
                    TCGEN05_WAIT_LD();
                    TCGEN05_FENCE_BEFORE();
                    BAR_ARRIVE(BAR_H2B, 288);
                    uint32_t o[16];
#pragma unroll
                    for (int j = 0; j < 16; j++) {
                        uint32_t p = pack_f16x2(__uint_as_float(r0[2 * j]), __uint_as_float(r0[2 * j + 1]));
                        o[j] = htanh2(hadd2u(p, bh2[64 + j]));
                    }
                    TCGEN05_ST_32X32B_X16(tb + 320u + warpoff, o);
#pragma unroll
                    for (int j = 0; j < 16; j++) {
                        uint32_t p = pack_f16x2(__uint_as_float(r1[2 * j]), __uint_as_float(r1[2 * j + 1]));
                        o[j] = htanh2(hadd2u(p, bh2[80 + j]));
                    }
                    TCGEN05_ST_32X32B_X16(tb + 336u + warpoff, o);
                    TCGEN05_WAIT_ST();
                }
                TCGEN05_FENCE_BEFORE();
                BAR_ARRIVE(BAR_H2, 288);

                // E3-lo: D3 cols [384,416) -> RK4 -> AZ[448,464)
                MBARRIER_WAIT_PARITY(sb + SM_CA, pca); pca ^= 1u;
                TCGEN05_FENCE_AFTER();
                {
                    uint32_t r[32];
                    TCGEN05_LD_32X32B_X32(r, tb + 384u + warpoff);
                    TCGEN05_WAIT_LD();
                    float zin[32];
                    if (s == 0) {
#pragma unroll
                        for (int j = 0; j < 32; j++) {
                            float f = __uint_as_float(r[j]) + b3s[j];
                            acc[j] = f;
                            zin[j] = fmaf(0.5f * DT_F, f, zc[j]);
                        }
                    } else if (s == 1) {
#pragma unroll
                        for (int j = 0; j < 32; j++) {
                            float f = __uint_as_float(r[j]) + b3s[j];
                            acc[j] = fmaf(2.0f, f, acc[j]);
                            zin[j] = fmaf(0.5f * DT_F, f, zc[j]);
                        }
                    } else if (s == 2) {
#pragma unroll
                        for (int j = 0; j < 32; j++) {
                            float f = __uint_as_float(r[j]) + b3s[j];
                            acc[j] = fmaf(2.0f, f, acc[j]);
                            zin[j] = fmaf(DT_F, f, zc[j]);
                        }
                    } else {
#pragma unroll
                        for (int j = 0; j < 32; j++) {
                            float f = __uint_as_float(r[j]) + b3s[j];
                            acc[j] += f;
                            zc[j] = fmaf(DT_F / 6.0f, acc[j], zc[j]);
                            zin[j] = zc[j];
                        }
                    }
                    uint32_t o[16];
#pragma unroll
                    for (int j = 0; j < 16; j++) o[j] = pack_f16x2(zin[2 * j], zin[2 * j + 1]);
                    TCGEN05_ST_32X32B_X16(tb + 448u + warpoff, o);
                    TCGEN05_WAIT_ST();
                    TCGEN05_FENCE_BEFORE();
                    BAR_ARRIVE(BAR_Z, 288);
                }
            }
        } else {
            // ---- wg1 chain: E1h1, E2q1, E2q3, E3-hi ----
            uint32_t pc1 = 0, pc3 = 0, pcb = 0;
            for (int it = 0; it < NSTEPS * 4; ++it) {
                const int s = it & 3;

                // E1h1: D[256,384) -> AH1[64:128packed] (cols 192-255)
                MBARRIER_WAIT_PARITY(sb + SM_C1, pc1); pc1 ^= 1u;
                TCGEN05_FENCE_AFTER();
                epi_pair(tb, 256u, 192u, bh1 + 64, warpoff);
                epi_pair(tb, 320u, 224u, bh1 + 96, warpoff);
                TCGEN05_FENCE_BEFORE();
                BAR_ARRIVE(BAR_H1, 288);

                // E2q1: D1=[64,128) -> AH2[32:64packed] (cols 288-319)
                MBARRIER_WAIT_PARITY(sb + SM_C1, pc1); pc1 ^= 1u;
                TCGEN05_FENCE_AFTER();
                epi_pair(tb, 64u, 288u, bh2 + 32, warpoff);
                TCGEN05_FENCE_BEFORE();
                BAR_ARRIVE(BAR_H2B, 288);

                // E2q3: D0=[0,64) -> AH2[96:128packed] (cols 352-383)
                MBARRIER_WAIT_PARITY(sb + SM_C3, pc3); pc3 ^= 1u;
                TCGEN05_FENCE_AFTER();
                epi_pair(tb, 0u, 352u, bh2 + 96, warpoff);
                TCGEN05_FENCE_BEFORE();
                BAR_ARRIVE(BAR_H2, 288);

                // E3-hi: D3 cols [416,448) -> RK4 -> AZ[464,480)
                MBARRIER_WAIT_PARITY(sb + SM_CB, pcb); pcb ^= 1u;
                TCGEN05_FENCE_AFTER();
                {
                    uint32_t r[32];
                    TCGEN05_LD_32X32B_X32(r, tb + 416u + warpoff);
                    TCGEN05_WAIT_LD();
                    float zin[32];
                    if (s == 0) {
#pragma unroll
                        for (int j = 0; j < 32; j++) {
                            float f = __uint_as_float(r[j]) + b3s[j];
                            acc[j] = f;
                            zin[j] = fmaf(0.5f * DT_F, f, zc[j]);
                        }
                    } else if (s == 1) {
#pragma unroll
                        for (int j = 0; j < 32; j++) {
                            float f = __uint_as_float(r[j]) + b3s[j];
                            acc[j] = fmaf(2.0f, f, acc[j]);
                            zin[j] = fmaf(0.5f * DT_F, f, zc[j]);
                        }
                    } else if (s == 2) {
#pragma unroll
                        for (int j = 0; j < 32; j++) {
                            float f = __uint_as_float(r[j]) + b3s[j];
                            acc[j] = fmaf(2.0f, f, acc[j]);
                            zin[j] = fmaf(DT_F, f, zc[j]);
                        }
                    } else {
#pragma unroll
                        for (int j = 0; j < 32; j++) {
                            float f = __uint_as_float(r[j]) + b3s[j];
                            acc[j] += f;
                            zc[j] = fmaf(DT_F / 6.0f, acc[j], zc[j]);
                            zin[j] = zc[j];
                        }
                    }
                    uint32_t o[16];
#pragma unroll
                    for (int j = 0; j < 16; j++) o[j] = pack_f16x2(zin[2 * j], zin[2 * j + 1]);
                    TCGEN05_ST_32X32B_X16(tb + 464u + warpoff, o);
                    TCGEN05_WAIT_ST();
                    TCGEN05_FENCE_BEFORE();
                    BAR_ARRIVE(BAR_Z, 288);
                }
            }
        }

        // ---- write result ----
        {
            float4* op = (float4*)(out + (size_t)row * DIMZ + wg * 32);
#pragma unroll
            for (int q = 0; q < 8; q++)
                op[q] = make_float4(zc[4 * q], zc[4 * q + 1], zc[4 * q + 2], zc[4 * q + 3]);
        }
    }

    __syncthreads();
    if (w == 8) TCGEN05_DEALLOC(tb, TMEM_NCOLS);
#endif  // CNF_HAS_TCGEN05
}

extern "C" void kernel_launch(void* const* d_in, const int* in_sizes, int n_in,
                              void* d_out, int out_size) {
    const float* z0 = (const float*)d_in[0];
    const float* W1 = (const float*)d_in[1];
    const float* b1 = (const float*)d_in[2];
    const float* W2 = (const float*)d_in[3];
    const float* b2 = (const float*)d_in[4];
    const float* W3 = (const float*)d_in[5];
    const float* b3 = (const float*)d_in[6];
    float* out = (float*)d_out;

    cudaFuncSetAttribute(cnf_rk4_kernel, cudaFuncAttributeMaxDynamicSharedMemorySize, SM_TOTAL);
    cnf_rk4_kernel<<<NTILES, NTHREADS, SM_TOTAL>>>(z0, W1, b1, W2, b2, W3, b3, out);
}

// round 13
// speedup vs baseline: 1.0163x; 1.0163x over previous
#include <cuda_runtime.h>
#include <cuda_fp16.h>
#include <cstdint>

#define DIMZ 64
#define HID 256
#define NBATCH 32768
#define NSTEPS 100
#define NTILES 128      // each CTA owns TWO M=128 tiles (256 rows), 1 wave
#define NTHREADS 288    // 8 worker warps + 1 MMA warp
#define DT_F 0.01f

#if defined(__CUDA_ARCH__)
#if defined(__CUDA_ARCH_FEAT_SM103_ALL) || \
    (defined(__CUDA_ARCH_SPECIFIC__) && (__CUDA_ARCH_SPECIFIC__ == 1030)) || \
    (defined(__CUDA_ARCH_HAS_FEATURE__) && defined(__CUDA_ARCH_FEAT_SM101_ALL))
#define CNF_HAS_TCGEN05 1
#else
#define CNF_HAS_TCGEN05 0
#endif
#else
#define CNF_HAS_TCGEN05 0
#endif

// ---- TMEM columns (512/512, D/AH buffers time-shared between tiles) ----
// [0,64)    D0   : G2 Q0/Q3      (also G1h0 D low half)
// [64,128)  D1   : G2 Q1         (also G1h0 D high half)
// [128,256) AH1  : layer-1 activations f16 packed
// [256,384) DW1  : G1h1 D (f32) -> reused as AH2 (f16 packed)
// [384,448) D2   : G2 Q2 -> reused as D3 (G3 f32 D; n0=[384,416), n1=[416,448))
// [448,480) AZ_A : tile-A z input f16 packed
// [480,512) AZ_B : tile-B z input f16 packed
#define TMEM_NCOLS 512u

// ---- named HW barriers ----
#define BAR_ZA 1    // 288: tile-A AZ ready
#define BAR_ZB 2    // 288: tile-B AZ ready
#define BAR_H1A 3   // 288
#define BAR_H1 4    // 288
#define BAR_H2B 5   // 288
#define BAR_H2 6    // 288
#define BAR_F0 7    // 288

// ---- SMEM byte layout ----
#define SM_TMEMPTR 0
#define SM_C0 8
#define SM_C1 16
#define SM_C2 24
#define SM_C3 32
#define SM_CA 40
#define SM_CB 48
#define SM_B1H 96
#define SM_B2H 608
#define SM_B3F 1120
#define SM_W1 2048
#define SM_W2 34816
#define SM_W3 165888
#define SM_TOTAL 198656

#define IDESC_F_N128 0x08200010u
#define IDESC_F_N64 0x08100010u
#define IDESC_F_N32 0x08080010u

static constexpr uint64_t DESC_BASE_SW128 =
    (uint64_t(2) << 61) | (uint64_t(1) << 46) | (uint64_t(64) << 32) | (uint64_t(1) << 16);

#if CNF_HAS_TCGEN05

__device__ __forceinline__ uint32_t smem_u32(const void* p) {
    uint32_t a;
    asm("{ .reg .u64 t; cvta.to.shared.u64 t, %1; cvt.u32.u64 %0, t; }" : "=r"(a) : "l"(p));
    return a;
}
__device__ __forceinline__ uint32_t elect1() {
    uint32_t r;
    asm volatile("{ .reg .pred p; elect.sync _|p, 0xFFFFFFFF; selp.b32 %0, 1, 0, p; }" : "=r"(r));
    return r;
}
__device__ __forceinline__ uint32_t swz128(uint32_t x) { return x ^ ((x >> 3) & 0x70); }

__device__ __forceinline__ uint32_t pack_f16x2(float lo, float hi) {
    uint32_t d;
    asm("cvt.rn.f16x2.f32 %0, %1, %2;" : "=r"(d) : "f"(hi), "f"(lo));
    return d;
}
__device__ __forceinline__ uint32_t hadd2u(uint32_t a, uint32_t b) {
    uint32_t d;
    asm("add.rn.f16x2 %0, %1, %2;" : "=r"(d) : "r"(a), "r"(b));
    return d;
}
__device__ __forceinline__ uint32_t htanh2(uint32_t a) {
    uint32_t d;
    asm("tanh.approx.f16x2 %0, %1;" : "=r"(d) : "r"(a));
    return d;
}

#define TCGEN05_ALLOC(smem_addr, nCols) \
    asm volatile("tcgen05.alloc.cta_group::1.sync.aligned.shared::cta.b32 [%0], %1;" \
                 :: "r"((uint32_t)(smem_addr)), "r"((uint32_t)(nCols)) : "memory")
#define TCGEN05_DEALLOC(tmem_addr, nCols) \
    asm volatile("tcgen05.dealloc.cta_group::1.sync.aligned.b32 %0, %1;" \
                 :: "r"(tmem_addr), "r"((uint32_t)(nCols)))
#define TCGEN05_WAIT_LD() asm volatile("tcgen05.wait::ld.sync.aligned;" ::: "memory")
#define TCGEN05_WAIT_ST() asm volatile("tcgen05.wait::st.sync.aligned;" ::: "memory")
#define TCGEN05_FENCE_BEFORE() asm volatile("tcgen05.fence::before_thread_sync;" ::: "memory")
#define TCGEN05_FENCE_AFTER() asm volatile("tcgen05.fence::after_thread_sync;" ::: "memory")
#define TCGEN05_COMMIT(mbar) \
    asm volatile("tcgen05.commit.cta_group::1.mbarrier::arrive::one.shared::cluster.b64 [%0];" \
                 :: "r"((uint32_t)(mbar)) : "memory")
#define MBARRIER_INIT(mbar, count) \
    asm volatile("mbarrier.init.shared.b64 [%0], %1;" \
                 :: "r"((uint32_t)(mbar)), "r"((uint32_t)(count)) : "memory")
#define FENCE_PROXY_ASYNC() asm volatile("fence.proxy.async.shared::cta;" ::: "memory")
#define BAR_ARRIVE(id, cnt) \
    asm volatile("bar.arrive %0, %1;" :: "r"((uint32_t)(id)), "r"((uint32_t)(cnt)) : "memory")
#define BAR_SYNC_N(id, cnt) \
    asm volatile("bar.sync %0, %1;" :: "r"((uint32_t)(id)), "r"((uint32_t)(cnt)) : "memory")

#define MBARRIER_WAIT_PARITY(mbar_smem_addr, phase_parity) do { \
    uint32_t _mbar = (uint32_t)(mbar_smem_addr); \
    uint32_t _parity = (uint32_t)(phase_parity); \
    uint32_t _done; \
    asm volatile( \
        "{\n\t" \
        ".reg .pred p;\n\t" \
        "mbarrier.try_wait.parity.acquire.cta.shared::cta.b64 p, [%1], %2;\n\t" \
        "selp.b32 %0, 1, 0, p;\n\t" \
        "}" \
        : "=r"(_done) : "r"(_mbar), "r"(_parity) : "memory"); \
    if (!_done) { \
        asm volatile( \
            "{\n\t" \
            ".reg .pred P1;\n\t" \
            "WAIT_LOOP_%=:\n\t" \
            "mbarrier.try_wait.parity.acquire.cta.shared::cta.b64 P1, [%0], %1, 0x989680;\n\t" \
            "@P1 bra.uni WAIT_DONE_%=;\n\t" \
            "bra.uni WAIT_LOOP_%=;\n\t" \
            "WAIT_DONE_%=:\n\t" \
            "}" \
            :: "r"(_mbar), "r"(_parity) : "memory"); \
    } \
} while (0)

#define TCGEN05_LD_32X32B_X32(r, tmem_addr) \
    asm volatile( \
        "tcgen05.ld.sync.aligned.32x32b.x32.b32 " \
        "{%0, %1, %2, %3, %4, %5, %6, %7, " \
        " %8, %9, %10, %11, %12, %13, %14, %15, " \
        " %16, %17, %18, %19, %20, %21, %22, %23, " \
        " %24, %25, %26, %27, %28, %29, %30, %31}, [%32];" \
        : "=r"((r)[0]),  "=r"((r)[1]),  "=r"((r)[2]),  "=r"((r)[3]), \
          "=r"((r)[4]),  "=r"((r)[5]),  "=r"((r)[6]),  "=r"((r)[7]), \
          "=r"((r)[8]),  "=r"((r)[9]),  "=r"((r)[10]), "=r"((r)[11]), \
          "=r"((r)[12]), "=r"((r)[13]), "=r"((r)[14]), "=r"((r)[15]), \
          "=r"((r)[16]), "=r"((r)[17]), "=r"((r)[18]), "=r"((r)[19]), \
          "=r"((r)[20]), "=r"((r)[21]), "=r"((r)[22]), "=r"((r)[23]), \
          "=r"((r)[24]), "=r"((r)[25]), "=r"((r)[26]), "=r"((r)[27]), \
          "=r"((r)[28]), "=r"((r)[29]), "=r"((r)[30]), "=r"((r)[31]) \
        : "r"(tmem_addr))

#define TCGEN05_ST_32X32B_X16(tmem_addr, r) \
    asm volatile( \
        "tcgen05.st.sync.aligned.32x32b.x16.b32 [%0], " \
        "{%1, %2, %3, %4, %5, %6, %7, %8, " \
        " %9, %10, %11, %12, %13, %14, %15, %16};" \
        :: "r"(tmem_addr), \
           "r"((r)[0]),  "r"((r)[1]),  "r"((r)[2]),  "r"((r)[3]), \
           "r"((r)[4]),  "r"((r)[5]),  "r"((r)[6]),  "r"((r)[7]), \
           "r"((r)[8]),  "r"((r)[9]),  "r"((r)[10]), "r"((r)[11]), \
           "r"((r)[12]), "r"((r)[13]), "r"((r)[14]), "r"((r)[15]) \
        : "memory")

__device__ __forceinline__ void mma_f16_ts(uint32_t d, uint32_t a, uint64_t bdesc,
                                           uint32_t idesc, uint32_t accum) {
    asm volatile(
        "{\n\t"
        ".reg .pred p;\n\t"
        "setp.ne.u32 p, %5, 0;\n\t"
        "tcgen05.mma.cta_group::1.kind::f16 [%0], [%1], %2, %3, {%4, %4, %4, %4}, p;\n\t"
        "}"
        :: "r"(d), "r"(a), "l"(bdesc), "r"(idesc), "r"(0u), "r"(accum)
        : "memory");
}

// LDTM 32 f32 D cols, pack+bias+tanh, STTM 16 packed cols. Ends drained.
__device__ __forceinline__ void epi32(uint32_t tb, uint32_t dsrc, uint32_t adst,
                                      const uint32_t* bias16, uint32_t warpoff) {
    uint32_t r[32];
    TCGEN05_LD_32X32B_X32(r, tb + dsrc + warpoff);
    TCGEN05_WAIT_LD();
    uint32_t o[16];
#pragma unroll
    for (int j = 0; j < 16; j++) {
        uint32_t p = pack_f16x2(__uint_as_float(r[2 * j]), __uint_as_float(r[2 * j + 1]));
        o[j] = htanh2(hadd2u(p, bias16[j]));
    }
    TCGEN05_ST_32X32B_X16(tb + adst + warpoff, o);
    TCGEN05_WAIT_ST();
}

// RK4 stage update core (inlined twice in E3, once per tile's state).
__device__ __forceinline__ void rk4_update(int s, const uint32_t* r, const float* b3s,
                                           float* zc, float* acc, float* zin) {
    if (s == 0) {
#pragma unroll
        for (int j = 0; j < 32; j++) {
            float f = __uint_as_float(r[j]) + b3s[j];
            acc[j] = f;
            zin[j] = fmaf(0.5f * DT_F, f, zc[j]);
        }
    } else if (s == 1) {
#pragma unroll
        for (int j = 0; j < 32; j++) {
            float f = __uint_as_float(r[j]) + b3s[j];
            acc[j] = fmaf(2.0f, f, acc[j]);
            zin[j] = fmaf(0.5f * DT_F, f, zc[j]);
        }
    } else if (s == 2) {
#pragma unroll
        for (int j = 0; j < 32; j++) {
            float f = __uint_as_float(r[j]) + b3s[j];
            acc[j] = fmaf(2.0f, f, acc[j]);
            zin[j] = fmaf(DT_F, f, zc[j]);
        }
    } else {
#pragma unroll
        for (int j = 0; j < 32; j++) {
            float f = __uint_as_float(r[j]) + b3s[j];
            acc[j] += f;
            zc[j] = fmaf(DT_F / 6.0f, acc[j], zc[j]);
            zin[j] = zc[j];
        }
    }
}

#endif  // CNF_HAS_TCGEN05

extern "C" __global__ void __launch_bounds__(NTHREADS, 1)
cnf_rk4_kernel(const float* __restrict__ z0,
               const float* __restrict__ W1, const float* __restrict__ b1,
               const float* __restrict__ W2, const float* __restrict__ b2,
               const float* __restrict__ W3, const float* __restrict__ b3,
               float* __restrict__ out) {
#if CNF_HAS_TCGEN05
    extern __shared__ char smem[];
    const uint32_t sb = smem_u32(smem);
    const int tid = threadIdx.x;
    const int w = tid >> 5;
    const int lane = tid & 31;

    if (w == 8) TCGEN05_ALLOC(sb + SM_TMEMPTR, TMEM_NCOLS);

    // ---- Weights -> f16 B-operand layouts in SMEM ----
    for (int i = tid; i < 64 * 256; i += NTHREADS) {
        int k = i >> 8, n = i & 255;
        *(__half*)(smem + SM_W1 + swz128((uint32_t)(n * 128 + k * 2))) = __float2half_rn(W1[i]);
    }
    for (int i = tid; i < 256 * 256; i += NTHREADS) {
        int k = i >> 8, n = i & 255;
        uint32_t off = (uint32_t)((((n >> 3) + (k >> 6) * 32) << 10) + ((n & 7) << 7) + ((k & 63) << 1));
        *(__half*)(smem + SM_W2 + swz128(off)) = __float2half_rn(W2[i]);
    }
    for (int i = tid; i < 256 * 64; i += NTHREADS) {
        int k = i >> 6, n = i & 63;
        uint32_t off = (uint32_t)((((n >> 3) + (k >> 6) * 8) << 10) + ((n & 7) << 7) + ((k & 63) << 1));
        *(__half*)(smem + SM_W3 + swz128(off)) = __float2half_rn(W3[i]);
    }
    for (int i = tid; i < 128; i += NTHREADS) {
        ((uint32_t*)(smem + SM_B1H))[i] = pack_f16x2(b1[2 * i], b1[2 * i + 1]);
        ((uint32_t*)(smem + SM_B2H))[i] = pack_f16x2(b2[2 * i], b2[2 * i + 1]);
    }
    for (int i = tid; i < 64; i += NTHREADS) ((float*)(smem + SM_B3F))[i] = b3[i];

    if (tid == 0) {
        MBARRIER_INIT(sb + SM_C0, 1); MBARRIER_INIT(sb + SM_C1, 1);
        MBARRIER_INIT(sb + SM_C2, 1); MBARRIER_INIT(sb + SM_C3, 1);
        MBARRIER_INIT(sb + SM_CA, 1); MBARRIER_INIT(sb + SM_CB, 1);
    }
    FENCE_PROXY_ASYNC();
    __syncthreads();

    uint32_t tb;
    asm volatile("ld.shared.b32 %0, [%1];" : "=r"(tb) : "r"(sb + SM_TMEMPTR));

    if (w == 8) {
        // ================= MMA-issue warp: ONE parameterized body =================
        const uint64_t dW1 = DESC_BASE_SW128 | (((uint64_t)((sb + SM_W1) >> 4)) & 0x3FFF);
        const uint64_t dW2 = DESC_BASE_SW128 | (((uint64_t)((sb + SM_W2) >> 4)) & 0x3FFF);
        const uint64_t dW3 = DESC_BASE_SW128 | (((uint64_t)((sb + SM_W3) >> 4)) & 0x3FFF);
        const uint64_t dW1b = dW1 + 1024;
        const uint64_t dW3b = dW3 + 256;

        for (int bi = 0; bi < NSTEPS * 8; ++bi) {
            const uint32_t tile = (uint32_t)(bi & 1);
            const uint32_t azcol = 448u + (tile << 5);
            const uint32_t zbar = BAR_ZA + tile;

            // P1: this tile's AZ ready (armed by its previous body's E3) -> G1
            BAR_SYNC_N(zbar, 288);
            TCGEN05_FENCE_AFTER();
            if (elect1()) {
                mma_f16_ts(tb + 0u,   tb + azcol,       dW1,      IDESC_F_N128, 0);
                mma_f16_ts(tb + 0u,   tb + azcol + 8u,  dW1 + 2,  IDESC_F_N128, 1);
                mma_f16_ts(tb + 0u,   tb + azcol + 16u, dW1 + 4,  IDESC_F_N128, 1);
                mma_f16_ts(tb + 0u,   tb + azcol + 24u, dW1 + 6,  IDESC_F_N128, 1);
                TCGEN05_COMMIT(sb + SM_C0);
                mma_f16_ts(tb + 256u, tb + azcol,       dW1b,     IDESC_F_N128, 0);
                mma_f16_ts(tb + 256u, tb + azcol + 8u,  dW1b + 2, IDESC_F_N128, 1);
                mma_f16_ts(tb + 256u, tb + azcol + 16u, dW1b + 4, IDESC_F_N128, 1);
                mma_f16_ts(tb + 256u, tb + azcol + 24u, dW1b + 6, IDESC_F_N128, 1);
                TCGEN05_COMMIT(sb + SM_C1);
            }
            // P2: AH1 low half -> Q0/Q1/Q2 K0-7
            BAR_SYNC_N(BAR_H1A, 288);
            TCGEN05_FENCE_AFTER();
            if (elect1()) {
#pragma unroll
                for (int ks = 0; ks < 8; ks++)
                    mma_f16_ts(tb + 0u, tb + 128u + (uint32_t)(ks * 8),
                               dW2 + (uint64_t)((ks & 3) * 2 + (ks >> 2) * 2048), IDESC_F_N64, ks > 0);
#pragma unroll
                for (int ks = 0; ks < 8; ks++)
                    mma_f16_ts(tb + 64u, tb + 128u + (uint32_t)(ks * 8),
                               dW2 + (uint64_t)(512 + (ks & 3) * 2 + (ks >> 2) * 2048), IDESC_F_N64, ks > 0);
#pragma unroll
                for (int ks = 0; ks < 8; ks++)
                    mma_f16_ts(tb + 384u, tb + 128u + (uint32_t)(ks * 8),
                               dW2 + (uint64_t)(1024 + (ks & 3) * 2 + (ks >> 2) * 2048), IDESC_F_N64, ks > 0);
            }
            // P3: AH1 full -> Q0/Q1/Q2 K8-15 (+C0, +C1, +C2)
            BAR_SYNC_N(BAR_H1, 288);
            TCGEN05_FENCE_AFTER();
            if (elect1()) {
#pragma unroll
                for (int ks = 8; ks < 16; ks++)
                    mma_f16_ts(tb + 0u, tb + 128u + (uint32_t)(ks * 8),
                               dW2 + (uint64_t)((ks & 3) * 2 + (ks >> 2) * 2048), IDESC_F_N64, 1);
                TCGEN05_COMMIT(sb + SM_C0);
#pragma unroll
                for (int ks = 8; ks < 16; ks++)
                    mma_f16_ts(tb + 64u, tb + 128u + (uint32_t)(ks * 8),
                               dW2 + (uint64_t)(512 + (ks & 3) * 2 + (ks >> 2) * 2048), IDESC_F_N64, 1);
                TCGEN05_COMMIT(sb + SM_C1);
#pragma unroll
                for (int ks = 8; ks < 16; ks++)
                    mma_f16_ts(tb + 384u, tb + 128u + (uint32_t)(ks * 8),
                               dW2 + (uint64_t)(1024 + (ks & 3) * 2 + (ks >> 2) * 2048), IDESC_F_N64, 1);
                TCGEN05_COMMIT(sb + SM_C2);
            }
            // P4: D0 reads drained (early release from E2q0) -> Q3 (+C3)
            BAR_SYNC_N(BAR_F0, 288);
            TCGEN05_FENCE_AFTER();
            if (elect1()) {
#pragma unroll
                for (int ks = 0; ks < 16; ks++)
                    mma_f16_ts(tb + 0u, tb + 128u + (uint32_t)(ks * 8),
                               dW2 + (uint64_t)(1536 + (ks & 3) * 2 + (ks >> 2) * 2048), IDESC_F_N64, ks > 0);
                TCGEN05_COMMIT(sb + SM_C3);
            }
            // P5: q2 LD-drained + q1 stored -> G3 n0/n1 K0-7
            BAR_SYNC_N(BAR_H2B, 288);
            TCGEN05_FENCE_AFTER();
            if (elect1()) {
#pragma unroll
                for (int ks = 0; ks < 8; ks++)
                    mma_f16_ts(tb + 384u, tb + 256u + (uint32_t)(ks * 8),
                               dW3 + (uint64_t)((ks & 3) * 2 + (ks >> 2) * 512), IDESC_F_N32, ks > 0);
#pragma unroll
                for (int ks = 0; ks < 8; ks++)
                    mma_f16_ts(tb + 416u, tb + 256u + (uint32_t)(ks * 8),
                               dW3b + (uint64_t)((ks & 3) * 2 + (ks >> 2) * 512), IDESC_F_N32, ks > 0);
            }
            // P6: AH2 full -> finish G3 (+CA, +CB)
            BAR_SYNC_N(BAR_H2, 288);
            TCGEN05_FENCE_AFTER();
            if (elect1()) {
#pragma unroll
                for (int ks = 8; ks < 16; ks++)
                    mma_f16_ts(tb + 384u, tb + 256u + (uint32_t)(ks * 8),
                               dW3 + (uint64_t)((ks & 3) * 2 + (ks >> 2) * 512), IDESC_F_N32, 1);
                TCGEN05_COMMIT(sb + SM_CA);
#pragma unroll
                for (int ks = 8; ks < 16; ks++)
                    mma_f16_ts(tb + 416u, tb + 256u + (uint32_t)(ks * 8),
                               dW3b + (uint64_t)((ks & 3) * 2 + (ks >> 2) * 512), IDESC_F_N32, 1);
                TCGEN05_COMMIT(sb + SM_CB);
            }
        }
    } else {
        // ================= worker warps (0-7): ONE parameterized body =================
        const int sp = w & 3;
        const int wg = w >> 2;
        const uint32_t warpoff = (uint32_t)sp << 21;
        const uint32_t wg64 = (uint32_t)(wg * 64);
        const uint32_t wg32 = (uint32_t)(wg * 32);
        const uint32_t wg16 = (uint32_t)(wg * 16);

        const uint32_t* bh1 = (const uint32_t*)(smem + SM_B1H);
        const uint32_t* bh2 = (const uint32_t*)(smem + SM_B2H);
        const float* b3s = (const float*)(smem + SM_B3F) + wg * 32;
        const uint32_t myCbar = (wg == 0) ? (sb + SM_CA) : (sb + SM_CB);

        const int rowA = blockIdx.x * 256 + sp * 32 + lane;
        const int rowB = rowA + 128;
        float zcA[32], accA[32], zcB[32], accB[32];
        {
            const float4* zpA = (const float4*)(z0 + (size_t)rowA * DIMZ + wg * 32);
            const float4* zpB = (const float4*)(z0 + (size_t)rowB * DIMZ + wg * 32);
#pragma unroll
            for (int q = 0; q < 8; q++) {
                float4 v = zpA[q];
                zcA[4 * q] = v.x; zcA[4 * q + 1] = v.y; zcA[4 * q + 2] = v.z; zcA[4 * q + 3] = v.w;
                float4 u = zpB[q];
                zcB[4 * q] = u.x; zcB[4 * q + 1] = u.y; zcB[4 * q + 2] = u.z; zcB[4 * q + 3] = u.w;
            }
#pragma unroll
            for (int j = 0; j < 32; j++) { accA[j] = 0.0f; accB[j] = 0.0f; }
        }
        // initial AZ_A + AZ_B; arm both tile-ready barriers
        {
            uint32_t o[16];
#pragma unroll
            for (int j = 0; j < 16; j++) o[j] = pack_f16x2(zcA[2 * j], zcA[2 * j + 1]);
            TCGEN05_ST_32X32B_X16(tb + 448u + wg16 + warpoff, o);
#pragma unroll
            for (int j = 0; j < 16; j++) o[j] = pack_f16x2(zcB[2 * j], zcB[2 * j + 1]);
            TCGEN05_ST_32X32B_X16(tb + 480u + wg16 + warpoff, o);
            TCGEN05_WAIT_ST();
            TCGEN05_FENCE_BEFORE();
            BAR_ARRIVE(BAR_ZA, 288);
            BAR_ARRIVE(BAR_ZB, 288);
        }

        uint32_t pc0 = 0, pc1 = 0, pc2 = 0, pc3 = 0, pcz = 0;

        for (int bi = 0; bi < NSTEPS * 8; ++bi) {
            const uint32_t tile = (uint32_t)(bi & 1);
            const int s = (bi >> 1) & 3;
            const uint32_t azcol = 448u + (tile << 5);
            const uint32_t zbar = BAR_ZA + tile;

            // E1 h0: D[0,128) -> AH1[0:64packed]
            MBARRIER_WAIT_PARITY(sb + SM_C0, pc0); pc0 ^= 1u;
            TCGEN05_FENCE_AFTER();
            epi32(tb, wg64,       128u + wg32,       bh1 + wg32,      warpoff);
            epi32(tb, wg64 + 32u, 128u + wg32 + 16u, bh1 + wg32 + 16, warpoff);
            TCGEN05_FENCE_BEFORE();
            BAR_ARRIVE(BAR_H1A, 288);

            // E1 h1: D[256,384) -> AH1[64:128packed]
            MBARRIER_WAIT_PARITY(sb + SM_C1, pc1); pc1 ^= 1u;
            TCGEN05_FENCE_AFTER();
            epi32(tb, 256u + wg64,       192u + wg32,       bh1 + 64 + wg32,      warpoff);
            epi32(tb, 256u + wg64 + 32u, 192u + wg32 + 16u, bh1 + 64 + wg32 + 16, warpoff);
            TCGEN05_FENCE_BEFORE();
            BAR_ARRIVE(BAR_H1, 288);

            // E2 q0 (D0) -> AH2[0:32packed]; early F0 after LD drain
            MBARRIER_WAIT_PARITY(sb + SM_C0, pc0); pc0 ^= 1u;
            TCGEN05_FENCE_AFTER();
            {
                uint32_t r[32];
                TCGEN05_LD_32X32B_X32(r, tb + wg32 + warpoff);
                TCGEN05_WAIT_LD();
                TCGEN05_FENCE_BEFORE();
                BAR_ARRIVE(BAR_F0, 288);
                uint32_t o[16];
#pragma unroll
                for (int j = 0; j < 16; j++) {
                    uint32_t p = pack_f16x2(__uint_as_float(r[2 * j]), __uint_as_float(r[2 * j + 1]));
                    o[j] = htanh2(hadd2u(p, bh2[wg16 + j]));
                }
                TCGEN05_ST_32X32B_X16(tb + 256u + wg16 + warpoff, o);
                TCGEN05_WAIT_ST();
            }

            // E2 q1 (D1) -> AH2[32:64packed]
            MBARRIER_WAIT_PARITY(sb + SM_C1, pc1); pc1 ^= 1u;
            TCGEN05_FENCE_AFTER();
            epi32(tb, 64u + wg32, 288u + wg16, bh2 + 32 + wg16, warpoff);

            // E2 q2 (D2) -> AH2[64:96packed]
            MBARRIER_WAIT_PARITY(sb + SM_C2, pc2); pc2 ^= 1u;
            TCGEN05_FENCE_AFTER();
            epi32(tb, 384u + wg32, 320u + wg16, bh2 + 64 + wg16, warpoff);
            TCGEN05_FENCE_BEFORE();
            BAR_ARRIVE(BAR_H2B, 288);

            // E2 q3 (D0) -> AH2[96:128packed]
            MBARRIER_WAIT_PARITY(sb + SM_C3, pc3); pc3 ^= 1u;
            TCGEN05_FENCE_AFTER();
            epi32(tb, wg32, 352u + wg16, bh2 + 96 + wg16, warpoff);
            TCGEN05_FENCE_BEFORE();
            BAR_ARRIVE(BAR_H2, 288);

            // E3 + RK4 update (per-tile state; only this block duplicates)
            MBARRIER_WAIT_PARITY(myCbar, pcz); pcz ^= 1u;
            TCGEN05_FENCE_AFTER();
            {
                uint32_t r[32];
                TCGEN05_LD_32X32B_X32(r, tb + 384u + wg32 + warpoff);
                TCGEN05_WAIT_LD();
                float zin[32];
                if (tile == 0) rk4_update(s, r, b3s, zcA, accA, zin);
                else           rk4_update(s, r, b3s, zcB, accB, zin);
                uint32_t o[16];
#pragma unroll
                for (int j = 0; j < 16; j++) o[j] = pack_f16x2(zin[2 * j], zin[2 * j + 1]);
                TCGEN05_ST_32X32B_X16(tb + azcol + wg16 + warpoff, o);
                TCGEN05_WAIT_ST();
                TCGEN05_FENCE_BEFORE();
                BAR_ARRIVE(zbar, 288);
            }
        }

        // ---- write results ----
        {
            float4* opA = (float4*)(out + (size_t)rowA * DIMZ + wg * 32);
            float4* opB = (float4*)(out + (size_t)rowB * DIMZ + wg * 32);
#pragma unroll
            for (int q = 0; q < 8; q++) {
                opA[q] = make_float4(zcA[4 * q], zcA[4 * q + 1], zcA[4 * q + 2], zcA[4 * q + 3]);
                opB[q] = make_float4(zcB[4 * q], zcB[4 * q + 1], zcB[4 * q + 2], zcB[4 * q + 3]);
            }
        }
    }

    __syncthreads();
    if (w == 8) TCGEN05_DEALLOC(tb, TMEM_NCOLS);
#endif  // CNF_HAS_TCGEN05
}

extern "C" void kernel_launch(void* const* d_in, const int* in_sizes, int n_in,
                              void* d_out, int out_size) {
    const float* z0 = (const float*)d_in[0];
    const float* W1 = (const float*)d_in[1];
    const float* b1 = (const float*)d_in[2];
    const float* W2 = (const float*)d_in[3];
    const float* b2 = (const float*)d_in[4];
    const float* W3 = (const float*)d_in[5];
    const float* b3 = (const float*)d_in[6];
    float* out = (float*)d_out;

    cudaFuncSetAttribute(cnf_rk4_kernel, cudaFuncAttributeMaxDynamicSharedMemorySize, SM_TOTAL);
    cnf_rk4_kernel<<<NTILES, NTHREADS, SM_TOTAL>>>(z0, W1, b1, W2, b2, W3, b3, out);
}

// round 15
// speedup vs baseline: 1.0776x; 1.0603x over previous
#include <cuda_runtime.h>
#include <cuda_fp16.h>
#include <cstdint>

#define DIMZ 64
#define HID 256
#define NBATCH 32768
#define NSTEPS 100
#define TILE_M 128
#define NTILES 256
#define NTHREADS 288   // 8 worker warps + 1 MMA warp
#define DT_F 0.01f

#if defined(__CUDA_ARCH__)
#if defined(__CUDA_ARCH_FEAT_SM103_ALL) || \
    (defined(__CUDA_ARCH_SPECIFIC__) && (__CUDA_ARCH_SPECIFIC__ == 1030)) || \
    (defined(__CUDA_ARCH_HAS_FEATURE__) && defined(__CUDA_ARCH_FEAT_SM101_ALL))
#define CNF_HAS_TCGEN05 1
#else
#define CNF_HAS_TCGEN05 0
#endif
#else
#define CNF_HAS_TCGEN05 0
#endif

// ---- TMEM columns ----
// [0,64)    D0   : G1 q0 D / G2 Q0 / G2 Q3
// [64,128)  D1   : G1 q1 D / G2 Q1
// [128,256) AH1  : layer-1 activations f16 packed
// [256,384) DW1  : G1 q2/q3 D (f32) -> reused as AH2 (f16 packed)
// [384,448) D2   : G2 Q2 -> reused as D3 (G3 f32 D; n0=[384,416), n1=[416,448))
// [448,480) AZ   : z input f16 packed
#define TMEM_NCOLS 512u

// ---- named HW barriers ----
#define BAR_Z0 1    // 160: wg0 workers + MMA warp
#define BAR_Z 2     // 288
#define BAR_H1A 3   // 288
#define BAR_H1 4    // 288
#define BAR_H2B 5   // 288
#define BAR_H2 6    // 288
#define BAR_F0 7    // 288

// ---- SMEM byte layout ----
#define SM_TMEMPTR 0
#define SM_C0 8
#define SM_C1 16
#define SM_C2 24
#define SM_C3 32
#define SM_CA 40
#define SM_CB 48
#define SM_B1H 96
#define SM_B2H 608
#define SM_B3F 1120
#define SM_W1 2048
#define SM_W2 34816
#define SM_W3 165888
#define SM_TOTAL 198656

#define IDESC_F_N64 0x08100010u
#define IDESC_F_N32 0x08080010u

static constexpr uint64_t DESC_BASE_SW128 =
    (uint64_t(2) << 61) | (uint64_t(1) << 46) | (uint64_t(64) << 32) | (uint64_t(1) << 16);

#if CNF_HAS_TCGEN05

__device__ __forceinline__ uint32_t smem_u32(const void* p) {
    uint32_t a;
    asm("{ .reg .u64 t; cvta.to.shared.u64 t, %1; cvt.u32.u64 %0, t; }" : "=r"(a) : "l"(p));
    return a;
}
__device__ __forceinline__ uint32_t elect1() {
    uint32_t r;
    asm volatile("{ .reg .pred p; elect.sync _|p, 0xFFFFFFFF; selp.b32 %0, 1, 0, p; }" : "=r"(r));
    return r;
}
__device__ __forceinline__ uint32_t swz128(uint32_t x) { return x ^ ((x >> 3) & 0x70); }

__device__ __forceinline__ uint32_t pack_f16x2(float lo, float hi) {
    uint32_t d;
    asm("cvt.rn.f16x2.f32 %0, %1, %2;" : "=r"(d) : "f"(hi), "f"(lo));
    return d;
}
__device__ __forceinline__ uint32_t hadd2u(uint32_t a, uint32_t b) {
    uint32_t d;
    asm("add.rn.f16x2 %0, %1, %2;" : "=r"(d) : "r"(a), "r"(b));
    return d;
}
__device__ __forceinline__ uint32_t htanh2(uint32_t a) {
    uint32_t d;
    asm("tanh.approx.f16x2 %0, %1;" : "=r"(d) : "r"(a));
    return d;
}

#define TCGEN05_ALLOC(smem_addr, nCols) \
    asm volatile("tcgen05.alloc.cta_group::1.sync.aligned.shared::cta.b32 [%0], %1;" \
                 :: "r"((uint32_t)(smem_addr)), "r"((uint32_t)(nCols)) : "memory")
#define TCGEN05_DEALLOC(tmem_addr, nCols) \
    asm volatile("tcgen05.dealloc.cta_group::1.sync.aligned.b32 %0, %1;" \
                 :: "r"(tmem_addr), "r"((uint32_t)(nCols)))
#define TCGEN05_WAIT_LD() asm volatile("tcgen05.wait::ld.sync.aligned;" ::: "memory")
#define TCGEN05_WAIT_ST() asm volatile("tcgen05.wait::st.sync.aligned;" ::: "memory")
#define TCGEN05_FENCE_BEFORE() asm volatile("tcgen05.fence::before_thread_sync;" ::: "memory")
#define TCGEN05_FENCE_AFTER() asm volatile("tcgen05.fence::after_thread_sync;" ::: "memory")
#define TCGEN05_COMMIT(mbar) \
    asm volatile("tcgen05.commit.cta_group::1.mbarrier::arrive::one.shared::cluster.b64 [%0];" \
                 :: "r"((uint32_t)(mbar)) : "memory")
#define MBARRIER_INIT(mbar, count) \
    asm volatile("mbarrier.init.shared.b64 [%0], %1;" \
                 :: "r"((uint32_t)(mbar)), "r"((uint32_t)(count)) : "memory")
#define FENCE_PROXY_ASYNC() asm volatile("fence.proxy.async.shared::cta;" ::: "memory")
#define BAR_ARRIVE(id, cnt) \
    asm volatile("bar.arrive %0, %1;" :: "r"((uint32_t)(id)), "r"((uint32_t)(cnt)) : "memory")
#define BAR_SYNC_N(id, cnt) \
    asm volatile("bar.sync %0, %1;" :: "r"((uint32_t)(id)), "r"((uint32_t)(cnt)) : "memory")

#define MBARRIER_WAIT_PARITY(mbar_smem_addr, phase_parity) do { \
    uint32_t _mbar = (uint32_t)(mbar_smem_addr); \
    uint32_t _parity = (uint32_t)(phase_parity); \
    uint32_t _done; \
    asm volatile( \
        "{\n\t" \
        ".reg .pred p;\n\t" \
        "mbarrier.try_wait.parity.acquire.cta.shared::cta.b64 p, [%1], %2;\n\t" \
        "selp.b32 %0, 1, 0, p;\n\t" \
        "}" \
        : "=r"(_done) : "r"(_mbar), "r"(_parity) : "memory"); \
    if (!_done) { \
        asm volatile( \
            "{\n\t" \
            ".reg .pred P1;\n\t" \
            "WAIT_LOOP_%=:\n\t" \
            "mbarrier.try_wait.parity.acquire.cta.shared::cta.b64 P1, [%0], %1, 0x989680;\n\t" \
            "@P1 bra.uni WAIT_DONE_%=;\n\t" \
            "bra.uni WAIT_LOOP_%=;\n\t" \
            "WAIT_DONE_%=:\n\t" \
            "}" \
            :: "r"(_mbar), "r"(_parity) : "memory"); \
    } \
} while (0)

#define TCGEN05_LD_32X32B_X32(r, tmem_addr) \
    asm volatile( \
        "tcgen05.ld.sync.aligned.32x32b.x32.b32 " \
        "{%0, %1, %2, %3, %4, %5, %6, %7, " \
        " %8, %9, %10, %11, %12, %13, %14, %15, " \
        " %16, %17, %18, %19, %20, %21, %22, %23, " \
        " %24, %25, %26, %27, %28, %29, %30, %31}, [%32];" \
        : "=r"((r)[0]),  "=r"((r)[1]),  "=r"((r)[2]),  "=r"((r)[3]), \
          "=r"((r)[4]),  "=r"((r)[5]),  "=r"((r)[6]),  "=r"((r)[7]), \
          "=r"((r)[8]),  "=r"((r)[9]),  "=r"((r)[10]), "=r"((r)[11]), \
          "=r"((r)[12]), "=r"((r)[13]), "=r"((r)[14]), "=r"((r)[15]), \
          "=r"((r)[16]), "=r"((r)[17]), "=r"((r)[18]), "=r"((r)[19]), \
          "=r"((r)[20]), "=r"((r)[21]), "=r"((r)[22]), "=r"((r)[23]), \
          "=r"((r)[24]), "=r"((r)[25]), "=r"((r)[26]), "=r"((r)[27]), \
          "=r"((r)[28]), "=r"((r)[29]), "=r"((r)[30]), "=r"((r)[31]) \
        : "r"(tmem_addr))

#define TCGEN05_ST_32X32B_X16(tmem_addr, r) \
    asm volatile( \
        "tcgen05.st.sync.aligned.32x32b.x16.b32 [%0], " \
        "{%1, %2, %3, %4, %5, %6, %7, %8, " \
        " %9, %10, %11, %12, %13, %14, %15, %16};" \
        :: "r"(tmem_addr), \
           "r"((r)[0]),  "r"((r)[1]),  "r"((r)[2]),  "r"((r)[3]), \
           "r"((r)[4]),  "r"((r)[5]),  "r"((r)[6]),  "r"((r)[7]), \
           "r"((r)[8]),  "r"((r)[9]),  "r"((r)[10]), "r"((r)[11]), \
           "r"((r)[12]), "r"((r)[13]), "r"((r)[14]), "r"((r)[15]) \
        : "memory")

__device__ __forceinline__ void mma_f16_ts(uint32_t d, uint32_t a, uint64_t bdesc,
                                           uint32_t idesc, uint32_t accum) {
    asm volatile(
        "{\n\t"
        ".reg .pred p;\n\t"
        "setp.ne.u32 p, %5, 0;\n\t"
        "tcgen05.mma.cta_group::1.kind::f16 [%0], [%1], %2, %3, {%4, %4, %4, %4}, p;\n\t"
        "}"
        :: "r"(d), "r"(a), "l"(bdesc), "r"(idesc), "r"(0u), "r"(accum)
        : "memory");
}

// LDTM 32 f32 D cols, pack+bias+tanh, STTM 16 packed cols. Ends drained.
__device__ __forceinline__ void epi32(uint32_t tb, uint32_t dsrc, uint32_t adst,
                                      const uint32_t* bias16, uint32_t warpoff) {
    uint32_t r[32];
    TCGEN05_LD_32X32B_X32(r, tb + dsrc + warpoff);
    TCGEN05_WAIT_LD();
    uint32_t o[16];
#pragma unroll
    for (int j = 0; j < 16; j++) {
        uint32_t p = pack_f16x2(__uint_as_float(r[2 * j]), __uint_as_float(r[2 * j + 1]));
        o[j] = htanh2(hadd2u(p, bias16[j]));
    }
    TCGEN05_ST_32X32B_X16(tb + adst + warpoff, o);
    TCGEN05_WAIT_ST();
}

#endif  // CNF_HAS_TCGEN05

extern "C" __global__ void __launch_bounds__(NTHREADS, 1)
cnf_rk4_kernel(const float* __restrict__ z0,
               const float* __restrict__ W1, const float* __restrict__ b1,
               const float* __restrict__ W2, const float* __restrict__ b2,
               const float* __restrict__ W3, const float* __restrict__ b3,
               float* __restrict__ out) {
#if CNF_HAS_TCGEN05
    extern __shared__ char smem[];
    const uint32_t sb = smem_u32(smem);
    const int tid = threadIdx.x;
    const int w = tid >> 5;
    const int lane = tid & 31;

    if (w == 8) TCGEN05_ALLOC(sb + SM_TMEMPTR, TMEM_NCOLS);

    // ---- Weights -> f16 B-operand layouts in SMEM ----
    for (int i = tid; i < 64 * 256; i += NTHREADS) {
        int k = i >> 8, n = i & 255;
        *(__half*)(smem + SM_W1 + swz128((uint32_t)(n * 128 + k * 2))) = __float2half_rn(W1[i]);
    }
    for (int i = tid; i < 256 * 256; i += NTHREADS) {
        int k = i >> 8, n = i & 255;
        uint32_t off = (uint32_t)((((n >> 3) + (k >> 6) * 32) << 10) + ((n & 7) << 7) + ((k & 63) << 1));
        *(__half*)(smem + SM_W2 + swz128(off)) = __float2half_rn(W2[i]);
    }
    for (int i = tid; i < 256 * 64; i += NTHREADS) {
        int k = i >> 6, n = i & 63;
        uint32_t off = (uint32_t)((((n >> 3) + (k >> 6) * 8) << 10) + ((n & 7) << 7) + ((k & 63) << 1));
        *(__half*)(smem + SM_W3 + swz128(off)) = __float2half_rn(W3[i]);
    }
    for (int i = tid; i < 128; i += NTHREADS) {
        ((uint32_t*)(smem + SM_B1H))[i] = pack_f16x2(b1[2 * i], b1[2 * i + 1]);
        ((uint32_t*)(smem + SM_B2H))[i] = pack_f16x2(b2[2 * i], b2[2 * i + 1]);
    }
    for (int i = tid; i < 64; i += NTHREADS) ((float*)(smem + SM_B3F))[i] = b3[i];

    if (tid == 0) {
        MBARRIER_INIT(sb + SM_C0, 1); MBARRIER_INIT(sb + SM_C1, 1);
        MBARRIER_INIT(sb + SM_C2, 1); MBARRIER_INIT(sb + SM_C3, 1);
        MBARRIER_INIT(sb + SM_CA, 1); MBARRIER_INIT(sb + SM_CB, 1);
    }
    FENCE_PROXY_ASYNC();
    __syncthreads();

    uint32_t tb;
    asm volatile("ld.shared.b32 %0, [%1];" : "=r"(tb) : "r"(sb + SM_TMEMPTR));

    if (w == 8) {
        // ================= MMA-issue warp =================
        const uint64_t dW1 = DESC_BASE_SW128 | (((uint64_t)((sb + SM_W1) >> 4)) & 0x3FFF);
        const uint64_t dW2 = DESC_BASE_SW128 | (((uint64_t)((sb + SM_W2) >> 4)) & 0x3FFF);
        const uint64_t dW3 = DESC_BASE_SW128 | (((uint64_t)((sb + SM_W3) >> 4)) & 0x3FFF);
        const uint64_t dW1q1 = dW1 + 512;    // W1 n-quarters (+64 rows = 512 units)
        const uint64_t dW1q2 = dW1 + 1024;
        const uint64_t dW1q3 = dW1 + 1536;
        const uint64_t dW3b = dW3 + 256;

        for (int it = 0; it < NSTEPS * 4; ++it) {
            // Z0: wg0's AZ half ready -> q0/q1 K0-1 (reads AZ[448,464))
            BAR_SYNC_N(BAR_Z0, 160);
            TCGEN05_FENCE_AFTER();
            if (elect1()) {
                mma_f16_ts(tb + 0u,  tb + 448u,      dW1,        IDESC_F_N64, 0);
                mma_f16_ts(tb + 0u,  tb + 448u + 8u, dW1 + 2,    IDESC_F_N64, 1);
                mma_f16_ts(tb + 64u, tb + 448u,      dW1q1,      IDESC_F_N64, 0);
                mma_f16_ts(tb + 64u, tb + 448u + 8u, dW1q1 + 2,  IDESC_F_N64, 1);
            }
            // Z: full AZ -> finish q0 (+C0), q1 (+C1), q2 (+C2), q3 (+C3)
            BAR_SYNC_N(BAR_Z, 288);
            TCGEN05_FENCE_AFTER();
            if (elect1()) {
                mma_f16_ts(tb + 0u,   tb + 448u + 16u, dW1 + 4,    IDESC_F_N64, 1);
                mma_f16_ts(tb + 0u,   tb + 448u + 24u, dW1 + 6,    IDESC_F_N64, 1);
                TCGEN05_COMMIT(sb + SM_C0);
                mma_f16_ts(tb + 64u,  tb + 448u + 16u, dW1q1 + 4,  IDESC_F_N64, 1);
                mma_f16_ts(tb + 64u,  tb + 448u + 24u, dW1q1 + 6,  IDESC_F_N64, 1);
                TCGEN05_COMMIT(sb + SM_C1);
                mma_f16_ts(tb + 256u, tb + 448u,       dW1q2,      IDESC_F_N64, 0);
                mma_f16_ts(tb + 256u, tb + 448u + 8u,  dW1q2 + 2,  IDESC_F_N64, 1);
                mma_f16_ts(tb + 256u, tb + 448u + 16u, dW1q2 + 4,  IDESC_F_N64, 1);
                mma_f16_ts(tb + 256u, tb + 448u + 24u, dW1q2 + 6,  IDESC_F_N64, 1);
                TCGEN05_COMMIT(sb + SM_C2);
                mma_f16_ts(tb + 320u, tb + 448u,       dW1q3,      IDESC_F_N64, 0);
                mma_f16_ts(tb + 320u, tb + 448u + 8u,  dW1q3 + 2,  IDESC_F_N64, 1);
                mma_f16_ts(tb + 320u, tb + 448u + 16u, dW1q3 + 4,  IDESC_F_N64, 1);
                mma_f16_ts(tb + 320u, tb + 448u + 24u, dW1q3 + 6,  IDESC_F_N64, 1);
                TCGEN05_COMMIT(sb + SM_C3);
            }
            // H1A: E1 stage A done (q0+q1 read, AH1[0:64packed] stored) -> Q0/Q1/Q2 K0-7
            BAR_SYNC_N(BAR_H1A, 288);
            TCGEN05_FENCE_AFTER();
            if (elect1()) {
#pragma unroll
                for (int ks = 0; ks < 8; ks++)
                    mma_f16_ts(tb + 0u, tb + 128u + (uint32_t)(ks * 8),
                               dW2 + (uint64_t)((ks & 3) * 2 + (ks >> 2) * 2048), IDESC_F_N64, ks > 0);
#pragma unroll
                for (int ks = 0; ks < 8; ks++)
                    mma_f16_ts(tb + 64u, tb + 128u + (uint32_t)(ks * 8),
                               dW2 + (uint64_t)(512 + (ks & 3) * 2 + (ks >> 2) * 2048), IDESC_F_N64, ks > 0);
#pragma unroll
                for (int ks = 0; ks < 8; ks++)
                    mma_f16_ts(tb + 384u, tb + 128u + (uint32_t)(ks * 8),
                               dW2 + (uint64_t)(1024 + (ks & 3) * 2 + (ks >> 2) * 2048), IDESC_F_N64, ks > 0);
            }
            // H1: E1 stage B done (AH1 full) -> Q0/Q1/Q2 K8-15 (+C0, +C1, +C2)
            BAR_SYNC_N(BAR_H1, 288);
            TCGEN05_FENCE_AFTER();
            if (elect1()) {
#pragma unroll
                for (int ks = 8; ks < 16; ks++)
                    mma_f16_ts(tb + 0u, tb + 128u + (uint32_t)(ks * 8),
                               dW2 + (uint64_t)((ks & 3) * 2 + (ks >> 2) * 2048), IDESC_F_N64, 1);
                TCGEN05_COMMIT(sb + SM_C0);
#pragma unroll
                for (int ks = 8; ks < 16; ks++)
                    mma_f16_ts(tb + 64u, tb + 128u + (uint32_t)(ks * 8),
                               dW2 + (uint64_t)(512 + (ks & 3) * 2 + (ks >> 2) * 2048), IDESC_F_N64, 1);
                TCGEN05_COMMIT(sb + SM_C1);
#pragma unroll
                for (int ks = 8; ks < 16; ks++)
                    mma_f16_ts(tb + 384u, tb + 128u + (uint32_t)(ks * 8),
                               dW2 + (uint64_t)(1024 + (ks & 3) * 2 + (ks >> 2) * 2048), IDESC_F_N64, 1);
                TCGEN05_COMMIT(sb + SM_C2);
            }
            // F0: D0 reads drained (early release from E2q0) -> Q3 (+C3)
            BAR_SYNC_N(BAR_F0, 288);
            TCGEN05_FENCE_AFTER();
            if (elect1()) {
#pragma unroll
                for (int ks = 0; ks < 16; ks++)
                    mma_f16_ts(tb + 0u, tb + 128u + (uint32_t)(ks * 8),
                               dW2 + (uint64_t)(1536 + (ks & 3) * 2 + (ks >> 2) * 2048), IDESC_F_N64, ks > 0);
                TCGEN05_COMMIT(sb + SM_C3);
            }
            // H2B: q2 LD-drained + q1 stored -> G3 n0/n1 K0-7
            BAR_SYNC_N(BAR_H2B, 288);
            TCGEN05_FENCE_AFTER();
            if (elect1()) {
#pragma unroll
                for (int ks = 0; ks < 8; ks++)
                    mma_f16_ts(tb + 384u, tb + 256u + (uint32_t)(ks * 8),
                               dW3 + (uint64_t)((ks & 3) * 2 + (ks >> 2) * 512), IDESC_F_N32, ks > 0);
#pragma unroll
                for (int ks = 0; ks < 8; ks++)
                    mma_f16_ts(tb + 416u, tb + 256u + (uint32_t)(ks * 8),
                               dW3b + (uint64_t)((ks & 3) * 2 + (ks >> 2) * 512), IDESC_F_N32, ks > 0);
            }
            // H2: AH2 full -> finish G3 n0 (+CA) then n1 (+CB)
            BAR_SYNC_N(BAR_H2, 288);
            TCGEN05_FENCE_AFTER();
            if (elect1()) {
#pragma unroll
                for (int ks = 8; ks < 16; ks++)
                    mma_f16_ts(tb + 384u, tb + 256u + (uint32_t)(ks * 8),
                               dW3 + (uint64_t)((ks & 3) * 2 + (ks >> 2) * 512), IDESC_F_N32, 1);
                TCGEN05_COMMIT(sb + SM_CA);
#pragma unroll
                for (int ks = 8; ks < 16; ks++)
                    mma_f16_ts(tb + 416u, tb + 256u + (uint32_t)(ks * 8),
                               dW3b + (uint64_t)((ks & 3) * 2 + (ks >> 2) * 512), IDESC_F_N32, 1);
                TCGEN05_COMMIT(sb + SM_CB);
            }
        }
    } else {
        // ================= worker warps (0-7) =================
        const int sp = w & 3;
        const int wg = w >> 2;
        const uint32_t warpoff = (uint32_t)sp << 21;
        const uint32_t wg32 = (uint32_t)(wg * 32);
        const uint32_t wg16 = (uint32_t)(wg * 16);

        const uint32_t* bh1 = (const uint32_t*)(smem + SM_B1H);
        const uint32_t* bh2 = (const uint32_t*)(smem + SM_B2H);
        const float* b3s = (const float*)(smem + SM_B3F) + wg * 32;
        const uint32_t myCbar = (wg == 0) ? (sb + SM_CA) : (sb + SM_CB);
        // E1 quarter data assignment (both wgs wait BOTH barriers per stage;
        // wg0 processes q0/q2, wg1 processes q1/q3)
        const uint32_t e1srcA = (wg == 0) ? 0u : 64u;       // q0 / q1 D cols
        const uint32_t e1srcB = (wg == 0) ? 256u : 320u;    // q2 / q3 D cols
        const uint32_t e1dstA = (wg == 0) ? 128u : 160u;    // packed dest
        const uint32_t e1dstB = (wg == 0) ? 192u : 224u;
        const uint32_t* e1bA = bh1 + (wg == 0 ? 0 : 32);
        const uint32_t* e1bB = bh1 + (wg == 0 ? 64 : 96);

        const int row = blockIdx.x * TILE_M + sp * 32 + lane;
        float zc[32], acc[32];
        {
            const float4* zp = (const float4*)(z0 + (size_t)row * DIMZ + wg * 32);
#pragma unroll
            for (int q = 0; q < 8; q++) {
                float4 v = zp[q];
                zc[4 * q] = v.x; zc[4 * q + 1] = v.y; zc[4 * q + 2] = v.z; zc[4 * q + 3] = v.w;
            }
#pragma unroll
            for (int j = 0; j < 32; j++) acc[j] = 0.0f;
        }
        // initial AZ
        {
            uint32_t o[16];
#pragma unroll
            for (int j = 0; j < 16; j++) o[j] = pack_f16x2(zc[2 * j], zc[2 * j + 1]);
            TCGEN05_ST_32X32B_X16(tb + 448u + wg16 + warpoff, o);
            TCGEN05_WAIT_ST();
            TCGEN05_FENCE_BEFORE();
            if (wg == 0) BAR_ARRIVE(BAR_Z0, 160);
            BAR_ARRIVE(BAR_Z, 288);
        }

        uint32_t pc0 = 0, pc1 = 0, pc2 = 0, pc3 = 0, pcz = 0;

        for (int it = 0; it < NSTEPS * 4; ++it) {
            const int s = it & 3;

            // E1 stage A: BOTH wgs wait C0 then C1 (parity invariant);
            // wg0 reads q0, wg1 reads q1 -> AH1[0:64packed]
            MBARRIER_WAIT_PARITY(sb + SM_C0, pc0); pc0 ^= 1u;
            MBARRIER_WAIT_PARITY(sb + SM_C1, pc1); pc1 ^= 1u;
            TCGEN05_FENCE_AFTER();
            epi32(tb, e1srcA,       e1dstA,       e1bA,      warpoff);
            epi32(tb, e1srcA + 32u, e1dstA + 16u, e1bA + 16, warpoff);
            TCGEN05_FENCE_BEFORE();
            BAR_ARRIVE(BAR_H1A, 288);

            // E1 stage B: BOTH wgs wait C2 then C3; wg0 reads q2, wg1 reads q3
            MBARRIER_WAIT_PARITY(sb + SM_C2, pc2); pc2 ^= 1u;
            MBARRIER_WAIT_PARITY(sb + SM_C3, pc3); pc3 ^= 1u;
            TCGEN05_FENCE_AFTER();
            epi32(tb, e1srcB,       e1dstB,       e1bB,      warpoff);
            epi32(tb, e1srcB + 32u, e1dstB + 16u, e1bB + 16, warpoff);
            TCGEN05_FENCE_BEFORE();
            BAR_ARRIVE(BAR_H1, 288);

            // E2 q0 (D0) -> AH2[0:32packed]; early F0 after LD drain
            MBARRIER_WAIT_PARITY(sb + SM_C0, pc0); pc0 ^= 1u;
            TCGEN05_FENCE_AFTER();
            {
                uint32_t r[32];
                TCGEN05_LD_32X32B_X32(r, tb + wg32 + warpoff);
                TCGEN05_WAIT_LD();
                TCGEN05_FENCE_BEFORE();
                BAR_ARRIVE(BAR_F0, 288);
                uint32_t o[16];
#pragma unroll
                for (int j = 0; j < 16; j++) {
                    uint32_t p = pack_f16x2(__uint_as_float(r[2 * j]), __uint_as_float(r[2 * j + 1]));
                    o[j] = htanh2(hadd2u(p, bh2[wg16 + j]));
                }
                TCGEN05_ST_32X32B_X16(tb + 256u + wg16 + warpoff, o);
                TCGEN05_WAIT_ST();
            }

            // E2 q1 (D1) -> AH2[32:64packed]
            MBARRIER_WAIT_PARITY(sb + SM_C1, pc1); pc1 ^= 1u;
            TCGEN05_FENCE_AFTER();
            epi32(tb, 64u + wg32, 288u + wg16, bh2 + 32 + wg16, warpoff);

            // E2 q2 (D2) -> AH2[64:96packed]; early H2B after LD drain
            MBARRIER_WAIT_PARITY(sb + SM_C2, pc2); pc2 ^= 1u;
            TCGEN05_FENCE_AFTER();
            {
                uint32_t r[32];
                TCGEN05_LD_32X32B_X32(r, tb + 384u + wg32 + warpoff);
                TCGEN05_WAIT_LD();
                TCGEN05_FENCE_BEFORE();
                BAR_ARRIVE(BAR_H2B, 288);
                uint32_t o[16];
#pragma unroll
                for (int j = 0; j < 16; j++) {
                    uint32_t p = pack_f16x2(__uint_as_float(r[2 * j]), __uint_as_float(r[2 * j + 1]));
                    o[j] = htanh2(hadd2u(p, bh2[64 + wg16 + j]));
                }
                TCGEN05_ST_32X32B_X16(tb + 320u + wg16 + warpoff, o);
                TCGEN05_WAIT_ST();
            }

            // E2 q3 (D0) -> AH2[96:128packed]
            MBARRIER_WAIT_PARITY(sb + SM_C3, pc3); pc3 ^= 1u;
            TCGEN05_FENCE_AFTER();
            epi32(tb, wg32, 352u + wg16, bh2 + 96 + wg16, warpoff);
            TCGEN05_FENCE_BEFORE();
            BAR_ARRIVE(BAR_H2, 288);

            // E3 + RK4 update: wg0 waits CA (feats 0-31), wg1 waits CB
            MBARRIER_WAIT_PARITY(myCbar, pcz); pcz ^= 1u;
            TCGEN05_FENCE_AFTER();
            {
                uint32_t r[32];
                TCGEN05_LD_32X32B_X32(r, tb + 384u + wg32 + warpoff);
                TCGEN05_WAIT_LD();
                float zin[32];
                if (s == 0) {
#pragma unroll
                    for (int j = 0; j < 32; j++) {
                        float f = __uint_as_float(r[j]) + b3s[j];
                        acc[j] = f;
                        zin[j] = fmaf(0.5f * DT_F, f, zc[j]);
                    }
                } else if (s == 1) {
#pragma unroll
                    for (int j = 0; j < 32; j++) {
                        float f = __uint_as_float(r[j]) + b3s[j];
                        acc[j] = fmaf(2.0f, f, acc[j]);
                        zin[j] = fmaf(0.5f * DT_F, f, zc[j]);
                    }
                } else if (s == 2) {
#pragma unroll
                    for (int j = 0; j < 32; j++) {
                        float f = __uint_as_float(r[j]) + b3s[j];
                        acc[j] = fmaf(2.0f, f, acc[j]);
                        zin[j] = fmaf(DT_F, f, zc[j]);
                    }
                } else {
#pragma unroll
                    for (int j = 0; j < 32; j++) {
                        float f = __uint_as_float(r[j]) + b3s[j];
                        acc[j] += f;
                        zc[j] = fmaf(DT_F / 6.0f, acc[j], zc[j]);
                        zin[j] = zc[j];
                    }
                }
                uint32_t o[16];
#pragma unroll
                for (int j = 0; j < 16; j++) o[j] = pack_f16x2(zin[2 * j], zin[2 * j + 1]);
                TCGEN05_ST_32X32B_X16(tb + 448u + wg16 + warpoff, o);
                TCGEN05_WAIT_ST();
                TCGEN05_FENCE_BEFORE();
                if (wg == 0) BAR_ARRIVE(BAR_Z0, 160);
                BAR_ARRIVE(BAR_Z, 288);
            }
        }

        // ---- write result ----
        {
            float4* op = (float4*)(out + (size_t)row * DIMZ + wg * 32);
#pragma unroll
            for (int q = 0; q < 8; q++)
                op[q] = make_float4(zc[4 * q], zc[4 * q + 1], zc[4 * q + 2], zc[4 * q + 3]);
        }
    }

    __syncthreads();
    if (w == 8) TCGEN05_DEALLOC(tb, TMEM_NCOLS);
#endif  // CNF_HAS_TCGEN05
}

extern "C" void kernel_launch(void* const* d_in, const int* in_sizes, int n_in,
                              void* d_out, int out_size) {
    const float* z0 = (const float*)d_in[0];
    const float* W1 = (const float*)d_in[1];
    const float* b1 = (const float*)d_in[2];
    const float* W2 = (const float*)d_in[3];
    const float* b2 = (const float*)d_in[4];
    const float* W3 = (const float*)d_in[5];
    const float* b3 = (const float*)d_in[6];
    float* out = (float*)d_out;

    cudaFuncSetAttribute(cnf_rk4_kernel, cudaFuncAttributeMaxDynamicSharedMemorySize, SM_TOTAL);
    cnf_rk4_kernel<<<NTILES, NTHREADS, SM_TOTAL>>>(z0, W1, b1, W2, b2, W3, b3, out);
}